// round 17
// baseline (speedup 1.0000x reference)
#include <cuda_runtime.h>
#include <cuda_fp16.h>
#include <cstdint>
#include <cstddef>

#define BB 4
#define NQ 16384
#define MP 4096
#define C1V 128
#define C2V 256
#define D0 256
#define D1 128
#define NTOT (BB*NQ)   // 65536

// ---------------- scratch (device globals; no allocation allowed) ----------------
__device__ float4 g_xyz2p[BB*MP];                  // packed xyz2 + norm
__device__ float  g_sc0[D0], g_sh0[D0], g_sc1[D1], g_sh1[D1];
__device__ int    g_pi[(size_t)NTOT*12];           // 4 tiles x top-3 indices per query
__device__ __half g_A1h[(size_t)NTOT*C1V];         // points1 fp16 (16 MB)
__device__ __half g_A2h[BB*MP*C2V];                // points2 fp16 (8 MB)
__device__ __half g_W0a[256*256];                  // w0[0:256,:]^T  (K-major fp16)
__device__ __half g_W0b[256*128];                  // w0[256:384,:]^T
__device__ __half g_W1h[128*256];                  // w1^T
__device__ __half g_P2Wh[BB*MP*D0];                // points2 @ w0a (8 MB, fp16)
__device__ __half g_G1h[(size_t)NTOT*D0];          // gathered first-layer partial fp16
__device__ __half g_Hh[(size_t)NTOT*D0];           // layer-1 activations fp16

// ---------------- PTX helpers ----------------
__device__ __forceinline__ uint32_t smem_u32(const void* p){
    uint32_t a;
    asm("{ .reg .u64 t; cvta.to.shared.u64 t, %1; cvt.u32.u64 %0, t; }" : "=r"(a) : "l"(p));
    return a;
}
__device__ __forceinline__ void cpa(uint32_t dst, const void* src){
    asm volatile("cp.async.ca.shared.global [%0], [%1], 16;" :: "r"(dst), "l"(src) : "memory");
}
__device__ __forceinline__ void cp_commit(){ asm volatile("cp.async.commit_group;" ::: "memory"); }
template<int NN> __device__ __forceinline__ void cp_wait(){ asm volatile("cp.async.wait_group %0;" :: "n"(NN) : "memory"); }

__device__ __forceinline__ void ldsm4(uint32_t& r0, uint32_t& r1, uint32_t& r2, uint32_t& r3, uint32_t addr){
    asm volatile("ldmatrix.sync.aligned.m8n8.x4.shared.b16 {%0,%1,%2,%3}, [%4];"
        : "=r"(r0), "=r"(r1), "=r"(r2), "=r"(r3) : "r"(addr));
}
__device__ __forceinline__ void mma16816(float* c, const uint32_t* a, const uint32_t* b){
    asm volatile(
        "mma.sync.aligned.m16n8k16.row.col.f32.f16.f16.f32 "
        "{%0,%1,%2,%3}, {%4,%5,%6,%7}, {%8,%9}, {%0,%1,%2,%3};"
        : "+f"(c[0]), "+f"(c[1]), "+f"(c[2]), "+f"(c[3])
        : "r"(a[0]), "r"(a[1]), "r"(a[2]), "r"(a[3]), "r"(b[0]), "r"(b[1]));
}

// exact top-3 with lexicographic (d, idx) ordering (matches top_k tie-break)
struct Top3 { float d0, d1, d2; int i0, i1, i2; };

__device__ __forceinline__ void merge3(Top3& a, float b0, int j0, float b1, int j1, float b2, int j2){
    float A[3] = {a.d0, a.d1, a.d2}; int AI[3] = {a.i0, a.i1, a.i2};
    float Bv[3] = {b0, b1, b2};      int BI[3] = {j0, j1, j2};
    float R[3]; int RI[3];
    int ia = 0, ib = 0;
    #pragma unroll
    for (int k = 0; k < 3; ++k){
        float av = A[ia], bv = Bv[ib];
        int aidx = AI[ia], bidx = BI[ib];
        bool ta = (av < bv) || (av == bv && aidx <= bidx);
        R[k]  = ta ? av : bv;
        RI[k] = ta ? aidx : bidx;
        ia += ta ? 1 : 0; ib += ta ? 0 : 1;
    }
    a.d0 = R[0]; a.d1 = R[1]; a.d2 = R[2];
    a.i0 = RI[0]; a.i1 = RI[1]; a.i2 = RI[2];
}
__device__ __forceinline__ void warp_reduce_top3(Top3& t){
    #pragma unroll
    for (int off = 16; off > 0; off >>= 1){
        float e0 = __shfl_xor_sync(0xFFFFFFFF, t.d0, off);
        float e1 = __shfl_xor_sync(0xFFFFFFFF, t.d1, off);
        float e2 = __shfl_xor_sync(0xFFFFFFFF, t.d2, off);
        int   j0 = __shfl_xor_sync(0xFFFFFFFF, t.i0, off);
        int   j1 = __shfl_xor_sync(0xFFFFFFFF, t.i1, off);
        int   j2 = __shfl_xor_sync(0xFFFFFFFF, t.i2, off);
        merge3(t, e0, j0, e1, j1, e2, j2);
    }
}

// ---------------- prep: pack xyz2 (+norm), BN scale/shift ----------------
__global__ void prep_kernel(const float* __restrict__ xyz2,
                            const float* __restrict__ G0, const float* __restrict__ B0,
                            const float* __restrict__ M0, const float* __restrict__ V0,
                            const float* __restrict__ G1, const float* __restrict__ B1,
                            const float* __restrict__ M1, const float* __restrict__ V1)
{
    int i = blockIdx.x*256 + threadIdx.x;
    if (i < BB*MP){
        float x = xyz2[i*3+0], y = xyz2[i*3+1], z = xyz2[i*3+2];
        g_xyz2p[i] = make_float4(x, y, z, x*x + y*y + z*z);
    }
    if (blockIdx.x == 0){
        int t = threadIdx.x;
        if (t < D0){ float s = G0[t]*rsqrtf(V0[t]+1e-3f); g_sc0[t]=s; g_sh0[t]=B0[t]-M0[t]*s; }
        if (t < D1){ float s = G1[t]*rsqrtf(V1[t]+1e-3f); g_sc1[t]=s; g_sh1[t]=B1[t]-M1[t]*s; }
    }
}

// ---------------- fp32 -> fp16 vector convert ----------------
__global__ void __launch_bounds__(256) f2h_kernel(const float4* __restrict__ in, __half2* __restrict__ out){
    int i = blockIdx.x*256 + threadIdx.x;
    float4 v = in[i];
    out[2*i+0] = __floats2half2_rn(v.x, v.y);
    out[2*i+1] = __floats2half2_rn(v.z, v.w);
}

// ---------------- weight transpose + fp16 (K-major for B operand) ----------------
__global__ void __launch_bounds__(256) wtrans_kernel(const float* __restrict__ w0, const float* __restrict__ w1){
    int t = blockIdx.x*256 + threadIdx.x;            // 0..131071
    if (t < 65536){
        int n = t >> 8, k = t & 255;
        g_W0a[n*256 + k] = __float2half_rn(w0[k*256 + n]);
    } else if (t < 98304){
        int u = t - 65536; int n = u >> 7, k = u & 127;  // n<256, k<128
        g_W0b[n*128 + k] = __float2half_rn(w0[(256 + k)*256 + n]);
    } else {
        int u = t - 98304; int n = u >> 8, k = u & 255;  // n<128, k<256
        g_W1h[n*256 + k] = __float2half_rn(w1[k*128 + n]);
    }
}

// ---------------- 3-NN tile pass: scalar loop, 256 queries/block (known-good) ----------
__global__ void __launch_bounds__(256) nn3_kernel(const float* __restrict__ xyz1)
{
    __shared__ float4 s[1024];                 // 16 KB
    const int tile = blockIdx.x & 3;
    const int q = (blockIdx.x >> 2)*256 + threadIdx.x;
    const int b = q >> 14;
    const float x = xyz1[q*3+0], y = xyz1[q*3+1], z = xyz1[q*3+2];
    const float ax = -2.f*x, ay = -2.f*y, az = -2.f*z;

    const float4* src = g_xyz2p + b*MP + tile*1024;
    for (int m = threadIdx.x; m < 1024; m += 256) s[m] = src[m];
    __syncthreads();

    float b0v = 3.0e37f, b1v = 3.0e37f, b2v = 3.0e37f;   // shifted space (d2 - n1)
    int   i0 = 0, i1 = 0, i2 = 0;

    #pragma unroll 8
    for (int m = 0; m < 1024; ++m){
        float4 t = s[m];
        float d = fmaf(az, t.z, fmaf(ay, t.y, fmaf(ax, t.x, t.w)));
        if (d < b2v){
            if (d < b1v){
                b2v = b1v; i2 = i1;
                if (d < b0v){ b1v = b0v; i1 = i0; b0v = d; i0 = m; }
                else        { b1v = d;   i1 = m; }
            } else { b2v = d; i2 = m; }
        }
    }

    const int base = tile*1024;
    int* o = g_pi + ((size_t)q*4 + tile)*3;
    o[0] = base + i0; o[1] = base + i1; o[2] = base + i2;
}

// --- gather with FUSED exact merge: 32 threads/query; lanes 0-11 hold candidates ------
__global__ void __launch_bounds__(256) gather_kernel(const float* __restrict__ xyz1, int qBase)
{
    const int t = blockIdx.x*256 + threadIdx.x;
    const int q = qBase + (t >> 5);
    const int lane = t & 31;
    const int b = q >> 14;

    const float x = xyz1[q*3+0], y = xyz1[q*3+1], z = xyz1[q*3+2];
    const float n1 = x*x + y*y + z*z;
    const float ax = -2.f*x, ay = -2.f*y, az = -2.f*z;

    Top3 tt = {3.0e37f, 3.0e37f, 3.0e37f, 0x7FFFFFFF, 0x7FFFFFFF, 0x7FFFFFFF};
    if (lane < 12){
        int gm = g_pi[(size_t)q*12 + lane];
        float4 p = g_xyz2p[b*MP + gm];
        tt.d0 = fmaf(az, p.z, fmaf(ay, p.y, fmaf(ax, p.x, p.w)));   // shifted
        tt.i0 = gm;
    }
    warp_reduce_top3(tt);          // exact lexicographic (d, idx) top-3

    float d0 = fmaxf(n1 + tt.d0, 1e-10f);
    float d1 = fmaxf(n1 + tt.d1, 1e-10f);
    float d2 = fmaxf(n1 + tt.d2, 1e-10f);
    float w0 = 1.f/d0, w1 = 1.f/d1, w2 = 1.f/d2;
    float inv = 1.f/(w0 + w1 + w2);
    w0 *= inv; w1 *= inv; w2 *= inv;

    const uint4* P = (const uint4*)g_P2Wh;     // row = 256 halves = 32 uint4
    const int base = b * (MP * 32);
    uint4 u0 = P[base + tt.i0*32 + lane];
    uint4 u1 = P[base + tt.i1*32 + lane];
    uint4 u2 = P[base + tt.i2*32 + lane];

    const __half2* h0 = (const __half2*)&u0;
    const __half2* h1 = (const __half2*)&u1;
    const __half2* h2 = (const __half2*)&u2;
    uint4 r;
    __half2* hr = (__half2*)&r;
    #pragma unroll
    for (int k = 0; k < 4; ++k){
        float2 a = __half22float2(h0[k]);
        float2 bb = __half22float2(h1[k]);
        float2 cc = __half22float2(h2[k]);
        float vx = w0*a.x + w1*bb.x + w2*cc.x;
        float vy = w0*a.y + w1*bb.y + w2*cc.y;
        hr[k] = __floats2half2_rn(vx, vy);
    }
    ((uint4*)g_G1h)[(size_t)q*32 + lane] = r;
}

// ---------------- fp16 tensor-core GEMM, 3-stage cp.async pipeline ----------------
#define STAGE_HALVES (128*40)
#define STAGE_BYTES  (2*STAGE_HALVES*2)

template<bool GATHER, bool BN, bool OUT_HALF>
__global__ void __launch_bounds__(256) gemm_h(
    const __half* __restrict__ A, const __half* __restrict__ Bt,
    const float* __restrict__ scale, const float* __restrict__ shift,
    void* __restrict__ outv, int K, int NcOut, int mOff)
{
    extern __shared__ __align__(16) __half dsm[];
    const uint32_t sBase = smem_u32(dsm);

    const int tid  = threadIdx.x;
    const int lane = tid & 31, warp = tid >> 5;
    const int wm = warp & 3, wn = warp >> 2;
    const int mBase = mOff + blockIdx.x * 128;
    const int nBase = blockIdx.y * 128;

    float acc[2][8][4];
    #pragma unroll
    for (int mt = 0; mt < 2; ++mt)
        #pragma unroll
        for (int nt = 0; nt < 8; ++nt)
            #pragma unroll
            for (int c = 0; c < 4; ++c) acc[mt][nt][c] = 0.f;

    const int g  = lane >> 3, lr = lane & 7;
    const uint32_t offA = (uint32_t)((wm*32 + (g&1)*8 + lr)*40 + (g>>1)*8);
    const uint32_t offB = (uint32_t)((wn*64 + (g>>1)*8 + lr)*40 + (g&1)*8);

    const int lrow = tid >> 1;                 // 0..127
    const int lseg2 = (tid & 1) * 2;           // 0 or 2
    const __half* Ag = A + (size_t)(mBase + lrow)*K + lseg2*8;
    const __half* Bg = Bt + (size_t)(nBase + lrow)*K + lseg2*8;
    const uint32_t dOff = (uint32_t)(lrow*40 + lseg2*8)*2;

    auto load_tile = [&](int kc, int stg){
        const uint32_t sA = sBase + (uint32_t)stg*STAGE_BYTES;
        const uint32_t sB = sA + STAGE_HALVES*2;
        const __half* a = Ag + kc*32;
        const __half* b = Bg + kc*32;
        cpa(sA + dOff,      a);
        cpa(sA + dOff + 16, a + 8);
        cpa(sB + dOff,      b);
        cpa(sB + dOff + 16, b + 8);
        cp_commit();
    };

    const int KC = K >> 5;
    load_tile(0, 0);
    if (KC > 1) load_tile(1, 1);

    int stg = 0;
    for (int kc = 0; kc < KC; ++kc){
        if (kc + 1 < KC) cp_wait<1>(); else cp_wait<0>();
        __syncthreads();

        const uint32_t sA = sBase + (uint32_t)stg*STAGE_BYTES;
        const uint32_t sB = sA + STAGE_HALVES*2;
        #pragma unroll
        for (int ks = 0; ks < 2; ++ks){
            uint32_t af[2][4];
            uint32_t bf[8][2];
            #pragma unroll
            for (int mt = 0; mt < 2; ++mt)
                ldsm4(af[mt][0], af[mt][1], af[mt][2], af[mt][3],
                      sA + (offA + mt*16*40 + ks*16)*2);
            #pragma unroll
            for (int ntp = 0; ntp < 4; ++ntp)
                ldsm4(bf[2*ntp][0], bf[2*ntp][1], bf[2*ntp+1][0], bf[2*ntp+1][1],
                      sB + (offB + ntp*16*40 + ks*16)*2);
            #pragma unroll
            for (int mt = 0; mt < 2; ++mt)
                #pragma unroll
                for (int nt = 0; nt < 8; ++nt)
                    mma16816(acc[mt][nt], af[mt], bf[nt]);
        }

        if (kc + 2 < KC){
            int ns = stg + 2; if (ns >= 3) ns -= 3;
            load_tile(kc + 2, ns);
        }
        if (++stg == 3) stg = 0;
    }

    // ---------------- epilogue ----------------
    #pragma unroll
    for (int mt = 0; mt < 2; ++mt){
        #pragma unroll
        for (int h = 0; h < 2; ++h){
            const int r = mBase + wm*32 + mt*16 + (lane >> 2) + h*8;
            const __half* g1row = GATHER ? (g_G1h + (size_t)r*D0) : nullptr;
            #pragma unroll
            for (int nt = 0; nt < 8; ++nt){
                const int c = nBase + wn*64 + nt*8 + (lane & 3)*2;
                float v0 = acc[mt][nt][h*2+0];
                float v1 = acc[mt][nt][h*2+1];
                if (GATHER){
                    float2 gg = __half22float2(*(const __half2*)(g1row + c));
                    v0 += gg.x; v1 += gg.y;
                }
                if (BN){
                    float2 sc = *(const float2*)(scale + c);
                    float2 sh = *(const float2*)(shift + c);
                    v0 = fmaxf(fmaf(v0, sc.x, sh.x), 0.f);
                    v1 = fmaxf(fmaf(v1, sc.y, sh.y), 0.f);
                }
                if (OUT_HALF){
                    __half2* o = (__half2*)outv;
                    o[((size_t)r*NcOut + c) >> 1] = __floats2half2_rn(v0, v1);
                } else {
                    float2* o = (float2*)outv;
                    o[((size_t)r*NcOut + c) >> 1] = make_float2(v0, v1);
                }
            }
        }
    }
}

#define GEMM_SMEM (3*STAGE_BYTES)   // 61440 bytes

// ---------------- launch ----------------
extern "C" void kernel_launch(void* const* d_in, const int* in_sizes, int n_in,
                              void* d_out, int out_size)
{
    const float* xyz1    = (const float*)d_in[0];
    const float* xyz2    = (const float*)d_in[1];
    const float* points1 = (const float*)d_in[2];
    const float* points2 = (const float*)d_in[3];
    const float* w0 = (const float*)d_in[4];
    const float* g0 = (const float*)d_in[5];
    const float* b0 = (const float*)d_in[6];
    const float* m0 = (const float*)d_in[7];
    const float* v0 = (const float*)d_in[8];
    const float* w1 = (const float*)d_in[9];
    const float* g1 = (const float*)d_in[10];
    const float* b1 = (const float*)d_in[11];
    const float* m1 = (const float*)d_in[12];
    const float* v1 = (const float*)d_in[13];
    float* out = (float*)d_out;

    void *pA1h=nullptr, *pA2h=nullptr, *pW0a=nullptr, *pW0b=nullptr, *pW1h=nullptr,
         *pP2Wh=nullptr, *pHh=nullptr, *pSc0=nullptr, *pSh0=nullptr, *pSc1=nullptr, *pSh1=nullptr;
    cudaGetSymbolAddress(&pA1h, g_A1h);
    cudaGetSymbolAddress(&pA2h, g_A2h);
    cudaGetSymbolAddress(&pW0a, g_W0a);
    cudaGetSymbolAddress(&pW0b, g_W0b);
    cudaGetSymbolAddress(&pW1h, g_W1h);
    cudaGetSymbolAddress(&pP2Wh, g_P2Wh);
    cudaGetSymbolAddress(&pHh,  g_Hh);
    cudaGetSymbolAddress(&pSc0, g_sc0);
    cudaGetSymbolAddress(&pSh0, g_sh0);
    cudaGetSymbolAddress(&pSc1, g_sc1);
    cudaGetSymbolAddress(&pSh1, g_sh1);

    static cudaStream_t s2 = nullptr, s3 = nullptr;
    static cudaEvent_t evFork = nullptr, evJoin = nullptr, evT = nullptr, evEnd = nullptr;
    if (!s2){
        cudaStreamCreateWithFlags(&s2, cudaStreamNonBlocking);
        cudaStreamCreateWithFlags(&s3, cudaStreamNonBlocking);
        cudaEventCreateWithFlags(&evFork, cudaEventDisableTiming);
        cudaEventCreateWithFlags(&evJoin, cudaEventDisableTiming);
        cudaEventCreateWithFlags(&evT,    cudaEventDisableTiming);
        cudaEventCreateWithFlags(&evEnd,  cudaEventDisableTiming);
        cudaFuncSetAttribute(gemm_h<false,false,true>, cudaFuncAttributeMaxDynamicSharedMemorySize, GEMM_SMEM);
        cudaFuncSetAttribute(gemm_h<true, true, true>, cudaFuncAttributeMaxDynamicSharedMemorySize, GEMM_SMEM);
        cudaFuncSetAttribute(gemm_h<false,true,false>, cudaFuncAttributeMaxDynamicSharedMemorySize, GEMM_SMEM);
    }

    // 1) prep on main stream (needed by both branches)
    prep_kernel<<<64, 256>>>(xyz2, g0, b0, m0, v0, g1, b1, m1, v1);

    // fork: side stream runs the GEMM-branch prologue concurrently with nn3
    cudaEventRecord(evFork, 0);
    cudaStreamWaitEvent(s2, evFork, 0);

    // branch B (stream s2): conversions + weight prep + gemm1
    f2h_kernel<<<BB*MP*C2V/4/256, 256, 0, s2>>>((const float4*)points2, (__half2*)pA2h);
    wtrans_kernel<<<512, 256, 0, s2>>>(w0, w1);
    gemm_h<false,false,true><<<dim3(128, 2), 256, GEMM_SMEM, s2>>>(
        (const __half*)pA2h, (const __half*)pW0a, nullptr, nullptr, pP2Wh, 256, 256, 0);
    f2h_kernel<<<NTOT*C1V/4/256, 256, 0, s2>>>((const float4*)points1, (__half2*)pA1h);
    cudaEventRecord(evJoin, s2);

    // branch A (main stream): 3-NN
    nn3_kernel<<<1024, 256>>>(xyz1);

    // join: tail needs gemm1/f2h (B) + nn3 (A)
    cudaStreamWaitEvent(0, evJoin, 0);

    // fork tail: second half on s3
    cudaEventRecord(evT, 0);
    cudaStreamWaitEvent(s3, evT, 0);

    // half 0 (main stream): rows [0, 32768)
    gather_kernel<<<4096, 256>>>(xyz1, 0);
    gemm_h<true,true,true><<<dim3(256, 2), 256, GEMM_SMEM>>>(
        (const __half*)pA1h, (const __half*)pW0b,
        (const float*)pSc0, (const float*)pSh0, pHh, 128, 256, 0);
    gemm_h<false,true,false><<<dim3(256, 1), 256, GEMM_SMEM>>>(
        (const __half*)pHh, (const __half*)pW1h,
        (const float*)pSc1, (const float*)pSh1, out, 256, 128, 0);

    // half 1 (stream s3): rows [32768, 65536)
    gather_kernel<<<4096, 256, 0, s3>>>(xyz1, 32768);
    gemm_h<true,true,true><<<dim3(256, 2), 256, GEMM_SMEM, s3>>>(
        (const __half*)pA1h, (const __half*)pW0b,
        (const float*)pSc0, (const float*)pSh0, pHh, 128, 256, 32768);
    gemm_h<false,true,false><<<dim3(256, 1), 256, GEMM_SMEM, s3>>>(
        (const __half*)pHh, (const __half*)pW1h,
        (const float*)pSc1, (const float*)pSh1, out, 256, 128, 32768);
    cudaEventRecord(evEnd, s3);

    // final join on main stream
    cudaStreamWaitEvent(0, evEnd, 0);
}